// round 1
// baseline (speedup 1.0000x reference)
#include <cuda_runtime.h>
#include <cstdint>

// SNNQNet: B=16384, S=256, H=128, A=18, T=8
// Fully fused: one block = 32 batch rows, all layers, all timesteps.
// Spikes stored as 1 byte per (row, neuron) holding the 8 timestep bits.
// GEMMs: predicated packed f32x2 adds (h, h+64 pairs share the spike predicate).

constexpr int Bn = 16384;
constexpr int Sn = 256;
constexpr int Hn = 128;
constexpr int An = 18;
constexpr int Tn = 8;

constexpr int BLOCK = 512;          // 16 warps
constexpr int RPB   = 32;           // batch rows per block
constexpr int RPW   = RPB / (BLOCK / 32);  // rows per warp = 2
constexpr int GRID  = Bn / RPB;     // 512 blocks

// ---- shared memory layout (bytes) ----
constexpr int OFF_WBUF = 0;                       // packed weights: up to 256*64 ull = 128KB
constexpr int OFF_SB   = 131072;                  // input spike bytes [RPB][256] = 8KB
constexpr int OFF_HA   = OFF_SB + RPB * Sn;       // hidden spikes A [RPB][128] = 4KB
constexpr int OFF_HB   = OFF_HA + RPB * Hn;       // hidden spikes B = 4KB
constexpr int OFF_WOUT = OFF_HB + RPB * Hn;       // W_out [128][18] f32 = 9216B
constexpr int OFF_BOUT = OFF_WOUT + Hn * An * 4;  // b_out (padded 32 floats)
constexpr int OFF_CB   = OFF_BOUT + 32 * 4;       // bias/gamma/beta 3*128 f32
constexpr int SMEM_BYTES = OFF_CB + 3 * Hn * 4;   // = 158336

__device__ __forceinline__ float f2lo(unsigned long long v) {
    return __uint_as_float((unsigned)v);
}
__device__ __forceinline__ float f2hi(unsigned long long v) {
    return __uint_as_float((unsigned)(v >> 32));
}
__device__ __forceinline__ unsigned long long pk(float a, float b) {
    return (unsigned long long)__float_as_uint(a) |
           ((unsigned long long)__float_as_uint(b) << 32);
}

// Two predicated packed-f32x2 adds sharing one predicate.
__device__ __forceinline__ void padd2(unsigned long long& u0, unsigned long long& u1,
                                      unsigned long long w0, unsigned long long w1,
                                      unsigned pred) {
    asm("{\n\t"
        ".reg .pred q;\n\t"
        "setp.ne.u32 q, %4, 0;\n\t"
        "@q add.rn.f32x2 %0, %0, %2;\n\t"
        "@q add.rn.f32x2 %1, %1, %3;\n\t"
        "}"
        : "+l"(u0), "+l"(u1)
        : "l"(w0), "l"(w1), "r"(pred));
}

// Butterfly-reduce 8 floats across the warp (all lanes end with the sum).
__device__ __forceinline__ void wred8(float* p) {
#pragma unroll
    for (int off = 16; off > 0; off >>= 1) {
#pragma unroll
        for (int t = 0; t < Tn; t++)
            p[t] += __shfl_xor_sync(0xffffffffu, p[t], off);
    }
}

// Load a K x 128 weight matrix into smem packed as pairs (h, h+64):
// wbuf[k*64 + j] = { W[k][j], W[k][j+64] }
__device__ __forceinline__ void load_w_packed(const float* __restrict__ W, int K,
                                              unsigned long long* wbuf) {
    float* wf = (float*)wbuf;
    for (int i = threadIdx.x; i < K * Hn; i += BLOCK) {
        int k = i >> 7;
        int h = i & 127;
        wf[(k * 64 + (h & 63)) * 2 + (h >> 6)] = W[i];
    }
}

__device__ __forceinline__ void load_cb3(const float* __restrict__ b,
                                         const float* __restrict__ g,
                                         const float* __restrict__ be, float* cb) {
    for (int i = threadIdx.x; i < Hn; i += BLOCK) {
        cb[i] = b[i];
        cb[128 + i] = g[i];
        cb[256 + i] = be[i];
    }
}

// One MS_ResBlock: u = hin @ W + b ; y = LN(u)*g + beta ; h_out = LIF(y + hin)
__device__ __forceinline__ void resblock(const unsigned long long* __restrict__ wbuf,
                                         const float* __restrict__ cb,
                                         const unsigned char* __restrict__ hin,
                                         unsigned char* __restrict__ hout) {
    const int warp = threadIdx.x >> 5;
    const int lane = threadIdx.x & 31;
    const unsigned long long bi0 = pk(cb[lane], cb[lane + 64]);
    const unsigned long long bi1 = pk(cb[lane + 32], cb[lane + 96]);
    const float g0 = cb[128 + lane],      g1 = cb[128 + lane + 64];
    const float g2 = cb[128 + lane + 32], g3 = cb[128 + lane + 96];
    const float e0 = cb[256 + lane],      e1 = cb[256 + lane + 64];
    const float e2 = cb[256 + lane + 32], e3 = cb[256 + lane + 96];

    for (int rr = 0; rr < RPW; rr++) {
        const int r = warp * RPW + rr;
        unsigned long long u0[Tn], u1[Tn];
#pragma unroll
        for (int t = 0; t < Tn; t++) { u0[t] = bi0; u1[t] = bi1; }

        const unsigned char* hr = hin + r * Hn;
#pragma unroll 4
        for (int k = 0; k < Hn; k++) {
            unsigned long long w0 = wbuf[k * 64 + lane];
            unsigned long long w1 = wbuf[k * 64 + lane + 32];
            unsigned byte = hr[k];
#pragma unroll
            for (int t = 0; t < Tn; t++)
                padd2(u0[t], u1[t], w0, w1, byte & (1u << t));
        }

        // LayerNorm over H=128 for each t
        float p[Tn];
#pragma unroll
        for (int t = 0; t < Tn; t++)
            p[t] = f2lo(u0[t]) + f2hi(u0[t]) + f2lo(u1[t]) + f2hi(u1[t]);
        wred8(p);
        float mu[Tn];
#pragma unroll
        for (int t = 0; t < Tn; t++) mu[t] = p[t] * (1.0f / 128.0f);
#pragma unroll
        for (int t = 0; t < Tn; t++) {
            float a = f2lo(u0[t]) - mu[t];
            float b = f2hi(u0[t]) - mu[t];
            float c = f2lo(u1[t]) - mu[t];
            float d = f2hi(u1[t]) - mu[t];
            p[t] = a * a + b * b + c * c + d * d;
        }
        wred8(p);
        float rs[Tn];
#pragma unroll
        for (int t = 0; t < Tn; t++)
            rs[t] = rsqrtf(p[t] * (1.0f / 128.0f) + 1e-5f);

        // residual spikes for this lane's 4 output neurons
        const unsigned q0 = hr[lane],      q1 = hr[lane + 64];
        const unsigned q2 = hr[lane + 32], q3 = hr[lane + 96];

        float v0 = 0.f, v1 = 0.f, v2 = 0.f, v3 = 0.f;
        unsigned n0 = 0, n1 = 0, n2 = 0, n3 = 0;
#pragma unroll
        for (int t = 0; t < Tn; t++) {
            float y0 = (f2lo(u0[t]) - mu[t]) * rs[t] * g0 + e0 + (float)((q0 >> t) & 1);
            float y1 = (f2hi(u0[t]) - mu[t]) * rs[t] * g1 + e1 + (float)((q1 >> t) & 1);
            float y2 = (f2lo(u1[t]) - mu[t]) * rs[t] * g2 + e2 + (float)((q2 >> t) & 1);
            float y3 = (f2hi(u1[t]) - mu[t]) * rs[t] * g3 + e3 + (float)((q3 >> t) & 1);
            v0 += (y0 - v0) * 0.5f; if (v0 >= 1.f) { n0 |= 1u << t; v0 = 0.f; }
            v1 += (y1 - v1) * 0.5f; if (v1 >= 1.f) { n1 |= 1u << t; v1 = 0.f; }
            v2 += (y2 - v2) * 0.5f; if (v2 >= 1.f) { n2 |= 1u << t; v2 = 0.f; }
            v3 += (y3 - v3) * 0.5f; if (v3 >= 1.f) { n3 |= 1u << t; v3 = 0.f; }
        }
        hout[r * Hn + lane]      = (unsigned char)n0;
        hout[r * Hn + lane + 64] = (unsigned char)n1;
        hout[r * Hn + lane + 32] = (unsigned char)n2;
        hout[r * Hn + lane + 96] = (unsigned char)n3;
    }
}

__global__ __launch_bounds__(BLOCK, 1) void snn_kernel(
    const float* __restrict__ x, const float* __restrict__ enc,
    const float* __restrict__ W_in, const float* __restrict__ b_in,
    const float* __restrict__ W_r1, const float* __restrict__ b_r1,
    const float* __restrict__ g_r1, const float* __restrict__ be_r1,
    const float* __restrict__ W_r2, const float* __restrict__ b_r2,
    const float* __restrict__ g_r2, const float* __restrict__ be_r2,
    const float* __restrict__ W_out, const float* __restrict__ b_out,
    float* __restrict__ out) {
    extern __shared__ char smem[];
    unsigned long long* wbuf = (unsigned long long*)(smem + OFF_WBUF);
    unsigned char* sb = (unsigned char*)(smem + OFF_SB);
    unsigned char* hA = (unsigned char*)(smem + OFF_HA);
    unsigned char* hB = (unsigned char*)(smem + OFF_HB);
    float* wout = (float*)(smem + OFF_WOUT);
    float* bout = (float*)(smem + OFF_BOUT);
    float* cb = (float*)(smem + OFF_CB);

    const int b0 = blockIdx.x * RPB;

    // Phase 0: Poisson encode -> spike bytes; stage W_in (packed), b_in, W_out, b_out
    for (int i = threadIdx.x; i < RPB * Sn; i += BLOCK) {
        int r = i >> 8;
        int s = i & 255;
        int b = b0 + r;
        float xv = x[b * Sn + s];
        unsigned byte = 0;
#pragma unroll
        for (int t = 0; t < Tn; t++) {
            float e = enc[((size_t)t * Bn + b) * Sn + s];
            if (e <= xv) byte |= 1u << t;
        }
        sb[i] = (unsigned char)byte;
    }
    load_w_packed(W_in, Sn, wbuf);
    for (int i = threadIdx.x; i < Hn; i += BLOCK) cb[i] = b_in[i];
    for (int i = threadIdx.x; i < Hn * An; i += BLOCK) wout[i] = W_out[i];
    if (threadIdx.x < An) bout[threadIdx.x] = b_out[threadIdx.x];
    __syncthreads();

    // Phase 1: GEMM1 (S=256 -> H=128) + LIF -> hA
    {
        const int warp = threadIdx.x >> 5;
        const int lane = threadIdx.x & 31;
        const unsigned long long bi0 = pk(cb[lane], cb[lane + 64]);
        const unsigned long long bi1 = pk(cb[lane + 32], cb[lane + 96]);
        for (int rr = 0; rr < RPW; rr++) {
            const int r = warp * RPW + rr;
            unsigned long long u0[Tn], u1[Tn];
#pragma unroll
            for (int t = 0; t < Tn; t++) { u0[t] = bi0; u1[t] = bi1; }
            const unsigned char* sbr = sb + r * Sn;
#pragma unroll 4
            for (int s = 0; s < Sn; s++) {
                unsigned long long w0 = wbuf[s * 64 + lane];
                unsigned long long w1 = wbuf[s * 64 + lane + 32];
                unsigned byte = sbr[s];
#pragma unroll
                for (int t = 0; t < Tn; t++)
                    padd2(u0[t], u1[t], w0, w1, byte & (1u << t));
            }
            float v0 = 0.f, v1 = 0.f, v2 = 0.f, v3 = 0.f;
            unsigned n0 = 0, n1 = 0, n2 = 0, n3 = 0;
#pragma unroll
            for (int t = 0; t < Tn; t++) {
                float a = f2lo(u0[t]), b = f2hi(u0[t]);
                float c = f2lo(u1[t]), d = f2hi(u1[t]);
                v0 += (a - v0) * 0.5f; if (v0 >= 1.f) { n0 |= 1u << t; v0 = 0.f; }
                v1 += (b - v1) * 0.5f; if (v1 >= 1.f) { n1 |= 1u << t; v1 = 0.f; }
                v2 += (c - v2) * 0.5f; if (v2 >= 1.f) { n2 |= 1u << t; v2 = 0.f; }
                v3 += (d - v3) * 0.5f; if (v3 >= 1.f) { n3 |= 1u << t; v3 = 0.f; }
            }
            hA[r * Hn + lane]      = (unsigned char)n0;
            hA[r * Hn + lane + 64] = (unsigned char)n1;
            hA[r * Hn + lane + 32] = (unsigned char)n2;
            hA[r * Hn + lane + 96] = (unsigned char)n3;
        }
    }
    __syncthreads();

    // Phase 2: ResBlock 1
    load_w_packed(W_r1, Hn, wbuf);
    load_cb3(b_r1, g_r1, be_r1, cb);
    __syncthreads();
    resblock(wbuf, cb, hA, hB);
    __syncthreads();

    // Phase 3: ResBlock 2
    load_w_packed(W_r2, Hn, wbuf);
    load_cb3(b_r2, g_r2, be_r2, cb);
    __syncthreads();
    resblock(wbuf, cb, hB, hA);
    __syncthreads();

    // Phase 4: readout GEMM (H=128 -> A=18) + non-spiking LIF + time mean.
    // mean_t v_t collapses to sum_t WGT[t] * u_t with WGT[t] = (1 - 2^-(8-t))/8.
    const float WGT[Tn] = {255.f / 2048.f, 127.f / 1024.f, 63.f / 512.f, 31.f / 256.f,
                           15.f / 128.f,   7.f / 64.f,     3.f / 32.f,   1.f / 16.f};
    for (int task = threadIdx.x; task < RPB * An; task += BLOCK) {
        int r = task / An;
        int a = task - r * An;
        float acc[Tn] = {0.f, 0.f, 0.f, 0.f, 0.f, 0.f, 0.f, 0.f};
        const unsigned char* hp = hA + r * Hn;
        for (int h = 0; h < Hn; h++) {
            unsigned byte = hp[h];
            float w = wout[h * An + a];
#pragma unroll
            for (int t = 0; t < Tn; t++)
                if (byte & (1u << t)) acc[t] += w;
        }
        float bo = bout[a];
        float o = 0.f;
#pragma unroll
        for (int t = 0; t < Tn; t++) o += WGT[t] * (acc[t] + bo);
        out[(size_t)(b0 + r) * An + a] = o;
    }
}

extern "C" void kernel_launch(void* const* d_in, const int* in_sizes, int n_in,
                              void* d_out, int out_size) {
    const float* x     = (const float*)d_in[0];
    const float* enc   = (const float*)d_in[1];
    const float* W_in  = (const float*)d_in[2];
    const float* b_in  = (const float*)d_in[3];
    const float* W_r1  = (const float*)d_in[4];
    const float* b_r1  = (const float*)d_in[5];
    const float* g_r1  = (const float*)d_in[6];
    const float* be_r1 = (const float*)d_in[7];
    const float* W_r2  = (const float*)d_in[8];
    const float* b_r2  = (const float*)d_in[9];
    const float* g_r2  = (const float*)d_in[10];
    const float* be_r2 = (const float*)d_in[11];
    const float* W_out = (const float*)d_in[12];
    const float* b_out = (const float*)d_in[13];
    float* out = (float*)d_out;

    cudaFuncSetAttribute(snn_kernel, cudaFuncAttributeMaxDynamicSharedMemorySize,
                         SMEM_BYTES);
    snn_kernel<<<GRID, BLOCK, SMEM_BYTES>>>(x, enc, W_in, b_in, W_r1, b_r1, g_r1,
                                            be_r1, W_r2, b_r2, g_r2, be_r2, W_out,
                                            b_out, out);
}

// round 6
// speedup vs baseline: 1.4415x; 1.4415x over previous
#include <cuda_runtime.h>
#include <cstdint>

// SNNQNet bit-exact scalar path, FMA2 + spike-LUT edition.
// B=16384, S=256, H=128, A=18, T=8. One block = 32 batch rows, fully fused.
// GEMMs: u[t] = fma2(w_pair, {s,s}, u[t]) -- bit-identical to predicated fp32 adds
// in k-ascending order (round-1 semantics, proven rel_err 9e-8).

constexpr int Bn = 16384;
constexpr int Sn = 256;
constexpr int Hn = 128;
constexpr int An = 18;
constexpr int Tn = 8;

constexpr int BLOCK = 512;                 // 16 warps
constexpr int RPB   = 32;                  // batch rows per block
constexpr int RPW   = RPB / (BLOCK / 32);  // rows per warp = 2
constexpr int GRID  = Bn / RPB;            // 512 blocks

typedef unsigned long long ull;

// ---- shared memory layout (bytes) ----
constexpr int OFF_WBUF = 0;                       // packed weights 256*64 ull = 128KB
constexpr int OFF_SB   = 131072;                  // input spike bytes [32][256]
constexpr int OFF_HA   = OFF_SB + RPB * Sn;       // hidden spikes A [32][128]
constexpr int OFF_HB   = OFF_HA + RPB * Hn;       // hidden spikes B
constexpr int OFF_WOUT = OFF_HB + RPB * Hn;       // W_out f32
constexpr int OFF_BOUT = OFF_WOUT + Hn * An * 4;  // b_out (32 floats)
constexpr int OFF_CB   = OFF_BOUT + 32 * 4;       // bias/gamma/beta
constexpr int OFF_LUT  = OFF_CB + 3 * Hn * 4;     // spike LUT [256][8] f32x2-pairs = 16KB
constexpr int SMEM_BYTES = OFF_LUT + 256 * 8 * 8; // 174720

__device__ __forceinline__ float f2lo(ull v) { return __uint_as_float((unsigned)v); }
__device__ __forceinline__ float f2hi(ull v) { return __uint_as_float((unsigned)(v >> 32)); }
__device__ __forceinline__ ull pk(float a, float b) {
    return (ull)__float_as_uint(a) | ((ull)__float_as_uint(b) << 32);
}

// u = w*s + u per 32-bit lane (packed f32x2). s in {0.0, 1.0} => bit-exact
// equivalent of conditional fp32 add.
__device__ __forceinline__ void fmad2(ull& u, ull w, ull s) {
    asm("fma.rn.f32x2 %0, %1, %2, %0;" : "+l"(u) : "l"(w), "l"(s));
}

// 16 fma2 covering 8 timesteps x (2 h-pairs), one k step.
__device__ __forceinline__ void fma_k(ull* u0, ull* u1, ull w0, ull w1,
                                      const ull* __restrict__ lutb) {
    const ulonglong2* lp = (const ulonglong2*)lutb;
    ulonglong2 sA = lp[0], sB = lp[1], sC = lp[2], sD = lp[3];
    fmad2(u0[0], w0, sA.x); fmad2(u1[0], w1, sA.x);
    fmad2(u0[1], w0, sA.y); fmad2(u1[1], w1, sA.y);
    fmad2(u0[2], w0, sB.x); fmad2(u1[2], w1, sB.x);
    fmad2(u0[3], w0, sB.y); fmad2(u1[3], w1, sB.y);
    fmad2(u0[4], w0, sC.x); fmad2(u1[4], w1, sC.x);
    fmad2(u0[5], w0, sC.y); fmad2(u1[5], w1, sC.y);
    fmad2(u0[6], w0, sD.x); fmad2(u1[6], w1, sD.x);
    fmad2(u0[7], w0, sD.y); fmad2(u1[7], w1, sD.y);
}

// Butterfly-reduce 8 floats across the warp.
__device__ __forceinline__ void wred8(float* p) {
#pragma unroll
    for (int off = 16; off > 0; off >>= 1) {
#pragma unroll
        for (int t = 0; t < Tn; t++)
            p[t] += __shfl_xor_sync(0xffffffffu, p[t], off);
    }
}

// Load K x 128 weights into smem packed as pairs (h, h+64).
__device__ __forceinline__ void load_w_packed(const float* __restrict__ W, int K,
                                              ull* wbuf) {
    float* wf = (float*)wbuf;
    for (int i = threadIdx.x; i < K * Hn; i += BLOCK) {
        int k = i >> 7;
        int h = i & 127;
        wf[(k * 64 + (h & 63)) * 2 + (h >> 6)] = W[i];
    }
}

__device__ __forceinline__ void load_cb3(const float* __restrict__ b,
                                         const float* __restrict__ g,
                                         const float* __restrict__ be, float* cb) {
    for (int i = threadIdx.x; i < Hn; i += BLOCK) {
        cb[i] = b[i];
        cb[128 + i] = g[i];
        cb[256 + i] = be[i];
    }
}

// One MS_ResBlock: u = hin @ W + b ; y = LN(u)*g + beta ; h_out = LIF(y + hin)
__device__ __forceinline__ void resblock(const ull* __restrict__ wbuf,
                                         const float* __restrict__ cb,
                                         const ull* __restrict__ lut,
                                         const unsigned char* __restrict__ hin,
                                         unsigned char* __restrict__ hout) {
    const int warp = threadIdx.x >> 5;
    const int lane = threadIdx.x & 31;
    const ull bi0 = pk(cb[lane], cb[lane + 64]);
    const ull bi1 = pk(cb[lane + 32], cb[lane + 96]);
    const float g0 = cb[128 + lane],      g1 = cb[128 + lane + 64];
    const float g2 = cb[128 + lane + 32], g3 = cb[128 + lane + 96];
    const float e0 = cb[256 + lane],      e1 = cb[256 + lane + 64];
    const float e2 = cb[256 + lane + 32], e3 = cb[256 + lane + 96];

    for (int rr = 0; rr < RPW; rr++) {
        const int r = warp * RPW + rr;
        ull u0[Tn], u1[Tn];
#pragma unroll
        for (int t = 0; t < Tn; t++) { u0[t] = bi0; u1[t] = bi1; }

        const unsigned char* hr = hin + r * Hn;
        const ull* wk = wbuf + lane;
#pragma unroll 2
        for (int k = 0; k < Hn; k++) {
            unsigned byte = hr[k];
            if (byte) {
                ull w0 = wk[k * 64], w1 = wk[k * 64 + 32];
                fma_k(u0, u1, w0, w1, lut + byte * 8);
            }
        }

        // LayerNorm over H=128 for each t
        float p[Tn];
#pragma unroll
        for (int t = 0; t < Tn; t++)
            p[t] = f2lo(u0[t]) + f2hi(u0[t]) + f2lo(u1[t]) + f2hi(u1[t]);
        wred8(p);
        float mu[Tn];
#pragma unroll
        for (int t = 0; t < Tn; t++) mu[t] = p[t] * (1.0f / 128.0f);
#pragma unroll
        for (int t = 0; t < Tn; t++) {
            float a = f2lo(u0[t]) - mu[t];
            float b = f2hi(u0[t]) - mu[t];
            float c = f2lo(u1[t]) - mu[t];
            float d = f2hi(u1[t]) - mu[t];
            p[t] = a * a + b * b + c * c + d * d;
        }
        wred8(p);
        float rs[Tn];
#pragma unroll
        for (int t = 0; t < Tn; t++)
            rs[t] = rsqrtf(p[t] * (1.0f / 128.0f) + 1e-5f);

        const unsigned q0 = hr[lane],      q1 = hr[lane + 64];
        const unsigned q2 = hr[lane + 32], q3 = hr[lane + 96];

        float v0 = 0.f, v1 = 0.f, v2 = 0.f, v3 = 0.f;
        unsigned n0 = 0, n1 = 0, n2 = 0, n3 = 0;
#pragma unroll
        for (int t = 0; t < Tn; t++) {
            float y0 = (f2lo(u0[t]) - mu[t]) * rs[t] * g0 + e0 + (float)((q0 >> t) & 1);
            float y1 = (f2hi(u0[t]) - mu[t]) * rs[t] * g1 + e1 + (float)((q1 >> t) & 1);
            float y2 = (f2lo(u1[t]) - mu[t]) * rs[t] * g2 + e2 + (float)((q2 >> t) & 1);
            float y3 = (f2hi(u1[t]) - mu[t]) * rs[t] * g3 + e3 + (float)((q3 >> t) & 1);
            v0 += (y0 - v0) * 0.5f; if (v0 >= 1.f) { n0 |= 1u << t; v0 = 0.f; }
            v1 += (y1 - v1) * 0.5f; if (v1 >= 1.f) { n1 |= 1u << t; v1 = 0.f; }
            v2 += (y2 - v2) * 0.5f; if (v2 >= 1.f) { n2 |= 1u << t; v2 = 0.f; }
            v3 += (y3 - v3) * 0.5f; if (v3 >= 1.f) { n3 |= 1u << t; v3 = 0.f; }
        }
        hout[r * Hn + lane]      = (unsigned char)n0;
        hout[r * Hn + lane + 64] = (unsigned char)n1;
        hout[r * Hn + lane + 32] = (unsigned char)n2;
        hout[r * Hn + lane + 96] = (unsigned char)n3;
    }
}

__global__ __launch_bounds__(BLOCK, 1) void snn_kernel(
    const float* __restrict__ x, const float* __restrict__ enc,
    const float* __restrict__ W_in, const float* __restrict__ b_in,
    const float* __restrict__ W_r1, const float* __restrict__ b_r1,
    const float* __restrict__ g_r1, const float* __restrict__ be_r1,
    const float* __restrict__ W_r2, const float* __restrict__ b_r2,
    const float* __restrict__ g_r2, const float* __restrict__ be_r2,
    const float* __restrict__ W_out, const float* __restrict__ b_out,
    float* __restrict__ out) {
    extern __shared__ char smem[];
    ull* wbuf = (ull*)(smem + OFF_WBUF);
    unsigned char* sb = (unsigned char*)(smem + OFF_SB);
    unsigned char* hA = (unsigned char*)(smem + OFF_HA);
    unsigned char* hB = (unsigned char*)(smem + OFF_HB);
    float* wout = (float*)(smem + OFF_WOUT);
    float* bout = (float*)(smem + OFF_BOUT);
    float* cb = (float*)(smem + OFF_CB);
    ull* lut = (ull*)(smem + OFF_LUT);

    const int b0 = blockIdx.x * RPB;

    // Phase 0: spike LUT, Poisson encode, stage weights/constants
    for (int i = threadIdx.x; i < 256 * 8; i += BLOCK) {
        int byte = i >> 3, t = i & 7;
        unsigned u = ((byte >> t) & 1) ? 0x3F800000u : 0u;
        lut[i] = ((ull)u << 32) | u;
    }
    for (int i = threadIdx.x; i < RPB * Sn; i += BLOCK) {
        int r = i >> 8;
        int s = i & 255;
        int b = b0 + r;
        float xv = x[b * Sn + s];
        unsigned byte = 0;
#pragma unroll
        for (int t = 0; t < Tn; t++) {
            float e = enc[((size_t)t * Bn + b) * Sn + s];
            if (e <= xv) byte |= 1u << t;
        }
        sb[i] = (unsigned char)byte;
    }
    load_w_packed(W_in, Sn, wbuf);
    for (int i = threadIdx.x; i < Hn; i += BLOCK) cb[i] = b_in[i];
    for (int i = threadIdx.x; i < Hn * An; i += BLOCK) wout[i] = W_out[i];
    if (threadIdx.x < An) bout[threadIdx.x] = b_out[threadIdx.x];
    __syncthreads();

    // Phase 1: GEMM1 (S=256 -> H=128) + LIF -> hA
    {
        const int warp = threadIdx.x >> 5;
        const int lane = threadIdx.x & 31;
        const ull bi0 = pk(cb[lane], cb[lane + 64]);
        const ull bi1 = pk(cb[lane + 32], cb[lane + 96]);
        for (int rr = 0; rr < RPW; rr++) {
            const int r = warp * RPW + rr;
            ull u0[Tn], u1[Tn];
#pragma unroll
            for (int t = 0; t < Tn; t++) { u0[t] = bi0; u1[t] = bi1; }
            const unsigned char* sbr = sb + r * Sn;
            const ull* wk = wbuf + lane;
#pragma unroll 2
            for (int k = 0; k < Sn; k++) {
                unsigned byte = sbr[k];
                if (byte) {
                    ull w0 = wk[k * 64], w1 = wk[k * 64 + 32];
                    fma_k(u0, u1, w0, w1, lut + byte * 8);
                }
            }
            float v0 = 0.f, v1 = 0.f, v2 = 0.f, v3 = 0.f;
            unsigned n0 = 0, n1 = 0, n2 = 0, n3 = 0;
#pragma unroll
            for (int t = 0; t < Tn; t++) {
                float a = f2lo(u0[t]), b = f2hi(u0[t]);
                float c = f2lo(u1[t]), d = f2hi(u1[t]);
                v0 += (a - v0) * 0.5f; if (v0 >= 1.f) { n0 |= 1u << t; v0 = 0.f; }
                v1 += (b - v1) * 0.5f; if (v1 >= 1.f) { n1 |= 1u << t; v1 = 0.f; }
                v2 += (c - v2) * 0.5f; if (v2 >= 1.f) { n2 |= 1u << t; v2 = 0.f; }
                v3 += (d - v3) * 0.5f; if (v3 >= 1.f) { n3 |= 1u << t; v3 = 0.f; }
            }
            hA[r * Hn + lane]      = (unsigned char)n0;
            hA[r * Hn + lane + 64] = (unsigned char)n1;
            hA[r * Hn + lane + 32] = (unsigned char)n2;
            hA[r * Hn + lane + 96] = (unsigned char)n3;
        }
    }
    __syncthreads();

    // Phase 2: ResBlock 1
    load_w_packed(W_r1, Hn, wbuf);
    load_cb3(b_r1, g_r1, be_r1, cb);
    __syncthreads();
    resblock(wbuf, cb, lut, hA, hB);
    __syncthreads();

    // Phase 3: ResBlock 2
    load_w_packed(W_r2, Hn, wbuf);
    load_cb3(b_r2, g_r2, be_r2, cb);
    __syncthreads();
    resblock(wbuf, cb, lut, hB, hA);
    __syncthreads();

    // Phase 4: readout GEMM (H=128 -> A=18) + non-spiking LIF + time mean.
    const float WGT[Tn] = {255.f / 2048.f, 127.f / 1024.f, 63.f / 512.f, 31.f / 256.f,
                           15.f / 128.f,   7.f / 64.f,     3.f / 32.f,   1.f / 16.f};
    for (int task = threadIdx.x; task < RPB * An; task += BLOCK) {
        int r = task / An;
        int a = task - r * An;
        float acc[Tn] = {0.f, 0.f, 0.f, 0.f, 0.f, 0.f, 0.f, 0.f};
        const unsigned char* hp = hA + r * Hn;
        for (int h = 0; h < Hn; h++) {
            unsigned byte = hp[h];
            float w = wout[h * An + a];
#pragma unroll
            for (int t = 0; t < Tn; t++)
                if (byte & (1u << t)) acc[t] += w;
        }
        float bo = bout[a];
        float o = 0.f;
#pragma unroll
        for (int t = 0; t < Tn; t++) o += WGT[t] * (acc[t] + bo);
        out[(size_t)(b0 + r) * An + a] = o;
    }
}

extern "C" void kernel_launch(void* const* d_in, const int* in_sizes, int n_in,
                              void* d_out, int out_size) {
    const float* x     = (const float*)d_in[0];
    const float* enc   = (const float*)d_in[1];
    const float* W_in  = (const float*)d_in[2];
    const float* b_in  = (const float*)d_in[3];
    const float* W_r1  = (const float*)d_in[4];
    const float* b_r1  = (const float*)d_in[5];
    const float* g_r1  = (const float*)d_in[6];
    const float* be_r1 = (const float*)d_in[7];
    const float* W_r2  = (const float*)d_in[8];
    const float* b_r2  = (const float*)d_in[9];
    const float* g_r2  = (const float*)d_in[10];
    const float* be_r2 = (const float*)d_in[11];
    const float* W_out = (const float*)d_in[12];
    const float* b_out = (const float*)d_in[13];
    float* out = (float*)d_out;

    cudaFuncSetAttribute(snn_kernel, cudaFuncAttributeMaxDynamicSharedMemorySize,
                         SMEM_BYTES);
    snn_kernel<<<GRID, BLOCK, SMEM_BYTES>>>(x, enc, W_in, b_in, W_r1, b_r1, g_r1,
                                            be_r1, W_r2, b_r2, g_r2, be_r2, W_out,
                                            b_out, out);
}